// round 14
// baseline (speedup 1.0000x reference)
#include <cuda_runtime.h>

// ---------------- problem constants ----------------
#define HW    36864        // 192*192 detector pixels
#define NSUB  18432        // H*W/2
#define BATCH 2
#define NV4   1769472      // 192^3/4
#define KCH   16           // alpha chunks (lanes) per ray
#define NW    1152         // HW/32 mask words
#define RBLK  864          // reduction blocks: 864*256*8 = NV4 exactly
#define RSTR  221184       // RBLK*256

#define F_INF __int_as_float(0x7f800000)

// ---------------- device scratch (static, no allocations) ----------------
__device__ float g_part[RBLK * 3];
__device__ float g_scalars[3];       // soft_min, dmin, inv_range
__device__ float g_pose[BATCH][16];  // R(9), source(3), t(3)
__device__ int   g_sorted[NSUB];     // subsample pixels in ascending order

// ---------------- launch 1: volume min/max partials (blocks 0..RBLK-1, 8x LDG.128 MLP)
//                  + subsample bitmap sort (block RBLK) + zero output ----------------
__global__ void __launch_bounds__(256) k_pre(const float4* __restrict__ vol,
                                             const int* __restrict__ sub,
                                             float4* __restrict__ out) {
    int gtid = blockIdx.x * 256 + threadIdx.x;
    if (gtid < (BATCH * HW) / 4) out[gtid] = make_float4(0.f, 0.f, 0.f, 0.f);

    if (blockIdx.x == RBLK) {
        // ---- sort subsample pixels ascending: bitmap + popc compaction ----
        __shared__ unsigned smask[NW];
        __shared__ unsigned spfx[NW];
        int t = threadIdx.x;
        for (int i = t; i < NW; i += 256) smask[i] = 0u;
        __syncthreads();
        for (int i = t; i < NSUB; i += 256) {
            int p = __ldg(&sub[i]);
            atomicOr(&smask[p >> 5], 1u << (p & 31));
        }
        __syncthreads();
        if (t < 32) {
            unsigned run = 0;
            for (int it = 0; it < NW / 32; it++) {
                int w = it * 32 + t;
                unsigned m = smask[w];
                unsigned p = (unsigned)__popc(m);
                unsigned sc = p;
                #pragma unroll
                for (int o = 1; o < 32; o <<= 1) {
                    unsigned v = __shfl_up_sync(0xffffffffu, sc, o);
                    if (t >= o) sc += v;
                }
                spfx[w] = run + sc - p;
                run += __shfl_sync(0xffffffffu, sc, 31);
            }
        }
        __syncthreads();
        for (int i = t; i < HW; i += 256) {
            unsigned m = smask[i >> 5];
            unsigned bit = 1u << (i & 31);
            if (m & bit) {
                int pos = (int)spfx[i >> 5] + __popc(m & (bit - 1u));
                g_sorted[pos] = i;
            }
        }
        return;
    }
    // ---- partial reductions: 8 independent float4 loads per thread (front-batched) ----
    float4 a[8];
    #pragma unroll
    for (int k = 0; k < 8; k++)
        a[k] = vol[gtid + k * RSTR];

    float smin = F_INF, omin = F_INF, omax = -F_INF;
    #pragma unroll
    for (int k = 0; k < 8; k++) {
        float vs[4] = {a[k].x, a[k].y, a[k].z, a[k].w};
        #pragma unroll
        for (int c = 0; c < 4; c++) {
            float v = vs[c];
            if (v > -800.0f) {
                omin = fminf(omin, v);
                omax = fmaxf(omax, v);
                if (v <= 350.0f) smin = fminf(smin, v);
            }
        }
    }
    __shared__ float s0[256], s1[256], s2[256];
    int t = threadIdx.x;
    s0[t] = smin; s1[t] = omin; s2[t] = omax;
    __syncthreads();
    for (int o = 128; o; o >>= 1) {
        if (t < o) {
            s0[t] = fminf(s0[t], s0[t + o]);
            s1[t] = fminf(s1[t], s1[t + o]);
            s2[t] = fmaxf(s2[t], s2[t + o]);
        }
        __syncthreads();
    }
    if (t == 0) {
        g_part[blockIdx.x * 3 + 0] = s0[0];
        g_part[blockIdx.x * 3 + 1] = s1[0];
        g_part[blockIdx.x * 3 + 2] = s2[0];
    }
}

// ---------------- launch 2: final reduction -> scalars; also pose precompute ----------------
__global__ void __launch_bounds__(512) k_scal(const float* __restrict__ rot,
                                              const float* __restrict__ tra) {
    __shared__ float s0[512], s1[512], s2[512];
    int t = threadIdx.x;
    float m0 = F_INF, m1 = F_INF, m2 = -F_INF;
    for (int i = t; i < RBLK; i += 512) {
        m0 = fminf(m0, g_part[i * 3 + 0]);
        m1 = fminf(m1, g_part[i * 3 + 1]);
        m2 = fmaxf(m2, g_part[i * 3 + 2]);
    }
    s0[t] = m0; s1[t] = m1; s2[t] = m2;
    if (t >= 504 && t < 504 + BATCH) {
        int b = t - 504;
        float cz, sz, cy, sy, cx, sx;
        sincosf(rot[b * 3 + 0], &sz, &cz);
        sincosf(rot[b * 3 + 1], &sy, &cy);
        sincosf(rot[b * 3 + 2], &sx, &cx);
        float R00 = cz * cy, R01 = -sz * cx + cz * sy * sx, R02 = sz * sx + cz * sy * cx;
        float R10 = sz * cy, R11 =  cz * cx + sz * sy * sx, R12 = -cz * sx + sz * sy * cx;
        float R20 = -sy,     R21 =  cy * sx,                R22 =  cy * cx;
        float tx = tra[b * 3 + 0] + 96.0f;
        float ty = tra[b * 3 + 1] + 96.0f;
        float tz = tra[b * 3 + 2] + 96.0f;
        float* P = g_pose[b];
        P[0] = R00; P[1] = R01; P[2] = R02;
        P[3] = R10; P[4] = R11; P[5] = R12;
        P[6] = R20; P[7] = R21; P[8] = R22;
        P[9]  = fmaf(R02, 300.0f, tx);   // source = R @ (0,0,300) + t
        P[10] = fmaf(R12, 300.0f, ty);
        P[11] = fmaf(R22, 300.0f, tz);
        P[12] = tx; P[13] = ty; P[14] = tz;
    }
    __syncthreads();
    for (int o = 256; o; o >>= 1) {
        if (t < o) {
            s0[t] = fminf(s0[t], s0[t + o]);
            s1[t] = fminf(s1[t], s1[t + o]);
            s2[t] = fmaxf(s2[t], s2[t + o]);
        }
        __syncthreads();
    }
    if (t == 0) {
        float smin = s0[0];
        float dmin = fminf(smin, s1[0]);
        float dmax = fmaxf(smin, s2[0]);
        g_scalars[0] = smin;
        g_scalars[1] = dmin;
        g_scalars[2] = 1.0f / (dmax - dmin);
    }
}

// Per-axis merge init at alpha=as. Branchless-advance state:
//  al   : alpha of next crossing (INF if none in volume)
//  pl   : direction-normalized plane counter (+1 per crossing)
//  adv  : d(alpha)/d(crossing), > 0 ; al = fmaf(pl, adv, base)
//  alim : advance valid while pl+1 <= alim
//  ci   : current cell; di: +-1
__device__ __forceinline__ void ax_init(float as, float src, float sd, float ss, float iv,
                                        float& al, float& pl, float& adv, float& base,
                                        float& alim, int& ci, int& di) {
    bool pos = (ss > 0.0f);
    di = pos ? 1 : -1;
    float dfa = (float)di;
    float t = fmaf(as, sd, src);           // position along this axis at alpha=as
    int p;
    if (pos) { p = (int)floorf(t) + 1; if (p < 0)   p = 0;   }
    else     { p = (int)ceilf(t)  - 1; if (p > 192) p = 192; }
    float pf = (float)p;
    al = (pf - src) * iv;
    if (al <= as) { p += di; pf = (float)p; al = (pf - src) * iv; }
    ci = pos ? (p - 1) : p;
    ci = min(191, max(0, ci));
    if (p < 0 || p > 192) al = F_INF;
    pl   = pf * dfa;
    adv  = dfa * iv;                       // > 0
    base = -src * iv;
    alim = pos ? 192.0f : 0.0f;
}

// ---------------- launch 3: raycast on RAW volume (KCH lanes/ray) ----------------
// density fold: out = inv * (sum step*vraw - dmin*(ae-as)) * ray_len,
// vraw = (v <= -800 ? smin : v), sampled at flipped x.
__global__ void __launch_bounds__(256) k_ray(const float* __restrict__ vol,
                                             float* __restrict__ out) {
    int gtid  = blockIdx.x * 256 + threadIdx.x;
    int group = gtid >> 4;                 // ray id
    int lane  = gtid & (KCH - 1);
    int b = (group >= NSUB) ? 1 : 0;
    int n = group - b * NSUB;
    int pix = g_sorted[n];

    float smin = g_scalars[0], dmin = g_scalars[1], inv = g_scalars[2];

    const float* P = g_pose[b];
    float R00 = P[0], R01 = P[1], R02 = P[2];
    float R10 = P[3], R11 = P[4], R12 = P[5];
    float R20 = P[6], R21 = P[7], R22 = P[8];
    float sx_ = P[9], sy_ = P[10], sz_ = P[11];
    float tx  = P[12], ty = P[13], tz = P[14];

    int piy  = pix / 192;
    int pixx = pix - piy * 192;
    float gx = ((float)pixx - 95.5f) * 2.0f;
    float gy = ((float)piy  - 95.5f) * 2.0f;
    const float gz = -300.0f;

    float tgx = fmaf(R02, gz, fmaf(R01, gy, R00 * gx)) + tx;
    float tgy = fmaf(R12, gz, fmaf(R11, gy, R10 * gx)) + ty;
    float tgz = fmaf(R22, gz, fmaf(R21, gy, R20 * gx)) + tz;

    float sdx = tgx - sx_, sdy = tgy - sy_, sdz = tgz - sz_;
    float ssx = (sdx == 0.0f) ? 1e-9f : sdx;
    float ssy = (sdy == 0.0f) ? 1e-9f : sdy;
    float ssz = (sdz == 0.0f) ? 1e-9f : sdz;
    float ivx = 1.0f / ssx, ivy = 1.0f / ssy, ivz = 1.0f / ssz;

    float ax0 = (0.0f   - sx_) * ivx, ax1 = (192.0f - sx_) * ivx;
    float ay0 = (0.0f   - sy_) * ivy, ay1 = (192.0f - sy_) * ivy;
    float az0 = (0.0f   - sz_) * ivz, az1 = (192.0f - sz_) * ivz;

    float amin = fmaxf(fmaxf(fminf(ax0, ax1), fminf(ay0, ay1)), fminf(az0, az1));
    amin = fmaxf(amin, 0.0f);
    float amax = fminf(fminf(fmaxf(ax0, ax1), fmaxf(ay0, ay1)), fmaxf(az0, az1));
    amax = fminf(amax, 1.0f);
    amax = fmaxf(amax, amin);

    float rl = sqrtf(fmaf(sdx, sdx, fmaf(sdy, sdy, sdz * sdz)));
    float da = (amax - amin) * (1.0f / (float)KCH);
    float as = fmaf((float)lane, da, amin);
    float ae = (lane == KCH - 1) ? amax : fmaf((float)(lane + 1), da, amin);

    float acc = 0.0f;
    if (ae > as) {
        float alx, aly, alz, plx, ply, plz, advx, advy, advz, basex, basey, basez;
        float alimx, alimy, alimz;
        int cxi, cyi, czi, dix, diy, diz;
        ax_init(as, sx_, sdx, ssx, ivx, alx, plx, advx, basex, alimx, cxi, dix);
        ax_init(as, sy_, sdy, ssy, ivy, aly, ply, advy, basey, alimy, cyi, diy);
        ax_init(as, sz_, sdz, ssz, ivz, alz, plz, advz, basez, alimz, czi, diz);

        // linear offset into RAW volume with x flipped: vol[(191-cx)*HW + cy*192 + cz]
        int off  = (191 - cxi) * HW + cyi * 192 + czi;
        int offdx = -dix * HW;       // x cell step moves raw index by -di*HW
        int offdy =  diy * 192;
        int offdz =  diz;

        float cur = fminf(alx, fminf(aly, alz));
        float prev = as;
        while (true) {
            float cseg = fminf(cur, ae);
            float v = __ldg(&vol[off]);
            v = (v <= -800.0f) ? smin : v;
            acc = fmaf(cseg - prev, v, acc);
            if (cur >= ae) break;
            prev = cur;
            // branchless 3-way advance; ONE validity predicate per axis
            bool sxm = (alx <= aly) & (alx <= alz);
            bool sym = (!sxm) & (aly <= alz);
            float plx2 = plx + 1.0f;
            float ply2 = ply + 1.0f;
            float plz2 = plz + 1.0f;
            bool vx = (plx2 <= alimx);
            bool vy = (ply2 <= alimy);
            bool vz = (plz2 <= alimz);
            float nax = vx ? fmaf(plx2, advx, basex) : F_INF;
            float nay = vy ? fmaf(ply2, advy, basey) : F_INF;
            float naz = vz ? fmaf(plz2, advz, basez) : F_INF;
            int   dox = vx ? offdx : 0;
            int   doy = vy ? offdy : 0;
            int   doz = vz ? offdz : 0;
            off += sxm ? dox : (sym ? doy : doz);
            plx = sxm ? plx2 : plx;   alx = sxm ? nax : alx;
            ply = sym ? ply2 : ply;   aly = sym ? nay : aly;
            bool szm = !(sxm | sym);
            plz = szm ? plz2 : plz;   alz = szm ? naz : alz;
            cur = fminf(alx, fminf(aly, alz));
        }
        acc = fmaf(-dmin, ae - as, acc);   // fold (v - dmin)
    }
    acc *= rl * inv;
    #pragma unroll
    for (int o = KCH / 2; o; o >>= 1)
        acc += __shfl_xor_sync(0xffffffffu, acc, o);
    if (lane == 0) out[b * HW + pix] = acc;
}

// ---------------- launch ----------------
extern "C" void kernel_launch(void* const* d_in, const int* in_sizes, int n_in,
                              void* d_out, int out_size) {
    const float* vol = (const float*)d_in[0];
    const float* rot = (const float*)d_in[1];
    const float* tra = (const float*)d_in[2];
    const int*   sub = (const int*)d_in[3];
    float* out = (float*)d_out;

    k_pre<<<RBLK + 1, 256>>>((const float4*)vol, sub, (float4*)out);
    k_scal<<<1, 512>>>(rot, tra);
    k_ray<<<(BATCH * NSUB * KCH) / 256, 256>>>(vol, out);
}

// round 15
// speedup vs baseline: 1.1192x; 1.1192x over previous
#include <cuda_runtime.h>

// ---------------- problem constants ----------------
#define HW    36864        // 192*192 detector pixels
#define NSUB  18432        // H*W/2
#define BATCH 2
#define NV4   1769472      // 192^3/4
#define KCH   16           // alpha chunks (lanes) per ray
#define NW    1152         // HW/32 mask words
#define RED   512          // reduction blocks (power of 2 for counter modulo)

#define F_INF __int_as_float(0x7f800000)

// ---------------- device scratch (static, no allocations) ----------------
__device__ float    g_part[RED * 3];
__device__ unsigned g_arrive;        // monotonic; (old & (RED-1)) == RED-1 -> last block
__device__ float    g_scalars[3];    // soft_min, dmin, inv_range
__device__ float    g_pose[BATCH][16];
__device__ int      g_sorted[NSUB];  // subsample pixels in ascending order

// ---------------- launch 1: volume min/max partials + last-block final reduce + pose
//                  (blocks 0..RED-1) | subsample bitmap sort (block RED) | zero output --------
__global__ void __launch_bounds__(256) k_pre(const float4* __restrict__ vol,
                                             const int* __restrict__ sub,
                                             const float* __restrict__ rot,
                                             const float* __restrict__ tra,
                                             float4* __restrict__ out) {
    int gtid = blockIdx.x * 256 + threadIdx.x;
    if (gtid < (BATCH * HW) / 4) out[gtid] = make_float4(0.f, 0.f, 0.f, 0.f);

    if (blockIdx.x == RED) {
        // ---- sort subsample pixels ascending: bitmap + popc compaction ----
        __shared__ unsigned smask[NW];
        __shared__ unsigned spfx[NW];
        int t = threadIdx.x;
        for (int i = t; i < NW; i += 256) smask[i] = 0u;
        __syncthreads();
        for (int i = t; i < NSUB; i += 256) {
            int p = __ldg(&sub[i]);
            atomicOr(&smask[p >> 5], 1u << (p & 31));
        }
        __syncthreads();
        if (t < 32) {
            unsigned run = 0;
            for (int it = 0; it < NW / 32; it++) {
                int w = it * 32 + t;
                unsigned m = smask[w];
                unsigned p = (unsigned)__popc(m);
                unsigned sc = p;
                #pragma unroll
                for (int o = 1; o < 32; o <<= 1) {
                    unsigned v = __shfl_up_sync(0xffffffffu, sc, o);
                    if (t >= o) sc += v;
                }
                spfx[w] = run + sc - p;
                run += __shfl_sync(0xffffffffu, sc, 31);
            }
        }
        __syncthreads();
        for (int i = t; i < HW; i += 256) {
            unsigned m = smask[i >> 5];
            unsigned bit = 1u << (i & 31);
            if (m & bit) {
                int pos = (int)spfx[i >> 5] + __popc(m & (bit - 1u));
                g_sorted[pos] = i;
            }
        }
        return;
    }

    // ---- partial reductions over volume (grid-stride, R12 shape) ----
    float smin = F_INF, omin = F_INF, omax = -F_INF;
    const int stride = RED * 256;
    for (int i = gtid; i < NV4; i += stride) {
        float4 v4 = vol[i];
        float vs[4] = {v4.x, v4.y, v4.z, v4.w};
        #pragma unroll
        for (int c = 0; c < 4; c++) {
            float v = vs[c];
            if (v > -800.0f) {
                omin = fminf(omin, v);
                omax = fmaxf(omax, v);
                if (v <= 350.0f) smin = fminf(smin, v);
            }
        }
    }
    __shared__ float s0[256], s1[256], s2[256];
    __shared__ bool  s_last;
    int t = threadIdx.x;
    s0[t] = smin; s1[t] = omin; s2[t] = omax;
    __syncthreads();
    for (int o = 128; o; o >>= 1) {
        if (t < o) {
            s0[t] = fminf(s0[t], s0[t + o]);
            s1[t] = fminf(s1[t], s1[t + o]);
            s2[t] = fmaxf(s2[t], s2[t + o]);
        }
        __syncthreads();
    }
    if (t == 0) {
        g_part[blockIdx.x * 3 + 0] = s0[0];
        g_part[blockIdx.x * 3 + 1] = s1[0];
        g_part[blockIdx.x * 3 + 2] = s2[0];
    }
    __threadfence();
    if (t == 0) {
        unsigned old = atomicAdd(&g_arrive, 1u);
        s_last = ((old & (RED - 1u)) == (RED - 1u));
    }
    __syncthreads();
    if (!s_last) return;
    __threadfence();

    // ---- last block: final reduce of RED partials + scalars + pose ----
    s0[t] = fminf(g_part[t * 3 + 0], g_part[(t + 256) * 3 + 0]);
    s1[t] = fminf(g_part[t * 3 + 1], g_part[(t + 256) * 3 + 1]);
    s2[t] = fmaxf(g_part[t * 3 + 2], g_part[(t + 256) * 3 + 2]);
    __syncthreads();
    for (int o = 128; o; o >>= 1) {
        if (t < o) {
            s0[t] = fminf(s0[t], s0[t + o]);
            s1[t] = fminf(s1[t], s1[t + o]);
            s2[t] = fmaxf(s2[t], s2[t + o]);
        }
        __syncthreads();
    }
    if (t == 0) {
        float sm = s0[0];
        float dmin = fminf(sm, s1[0]);
        float dmax = fmaxf(sm, s2[0]);
        g_scalars[0] = sm;
        g_scalars[1] = dmin;
        g_scalars[2] = 1.0f / (dmax - dmin);
    }
    if (t < BATCH) {
        int b = t;
        float cz, sz, cy, sy, cx, sx;
        sincosf(rot[b * 3 + 0], &sz, &cz);
        sincosf(rot[b * 3 + 1], &sy, &cy);
        sincosf(rot[b * 3 + 2], &sx, &cx);
        float R00 = cz * cy, R01 = -sz * cx + cz * sy * sx, R02 = sz * sx + cz * sy * cx;
        float R10 = sz * cy, R11 =  cz * cx + sz * sy * sx, R12 = -cz * sx + sz * sy * cx;
        float R20 = -sy,     R21 =  cy * sx,                R22 =  cy * cx;
        float tx = tra[b * 3 + 0] + 96.0f;
        float ty = tra[b * 3 + 1] + 96.0f;
        float tz = tra[b * 3 + 2] + 96.0f;
        float* P = g_pose[b];
        P[0] = R00; P[1] = R01; P[2] = R02;
        P[3] = R10; P[4] = R11; P[5] = R12;
        P[6] = R20; P[7] = R21; P[8] = R22;
        P[9]  = fmaf(R02, 300.0f, tx);   // source = R @ (0,0,300) + t
        P[10] = fmaf(R12, 300.0f, ty);
        P[11] = fmaf(R22, 300.0f, tz);
        P[12] = tx; P[13] = ty; P[14] = tz;
    }
}

// Per-axis merge init at alpha=as. Crossing alpha at absolute plane P is
// ALWAYS fmaf(P, iv, base), base = -src*iv — the same expression used for the
// amin/amax bounds, so the march can never step past a boundary plane while
// cur < ae <= amax (no per-iteration validity checks needed).
//  al  : alpha of first crossing with al > as
//  pl  : direction-normalized plane counter (+1 per crossing); alpha via
//        fmaf(pl, adv, base) == fmaf(P, iv, base) bitwise (sign flips exact)
//  ci  : current cell; di: +-1
__device__ __forceinline__ void ax_init(float as, float src, float sd, float ss,
                                        float iv, float base,
                                        float& al, float& pl, float& adv, int& ci, int& di) {
    bool pos = (ss > 0.0f);
    di = pos ? 1 : -1;
    float dfa = (float)di;
    float t = fmaf(as, sd, src);           // position along this axis at alpha=as
    int p;
    if (pos) { p = (int)floorf(t) + 1; if (p < 0)   p = 0;   }
    else     { p = (int)ceilf(t)  - 1; if (p > 192) p = 192; }
    float pf = (float)p;
    al = fmaf(pf, iv, base);
    if (al <= as) { p += di; pf = (float)p; al = fmaf(pf, iv, base); }
    ci = pos ? (p - 1) : p;
    ci = min(191, max(0, ci));
    pl  = pf * dfa;
    adv = dfa * iv;                        // > 0
}

// ---------------- launch 2: raycast on RAW volume (KCH lanes/ray) ----------------
// density fold: out = inv * (sum step*vraw - dmin*(ae-as)) * ray_len,
// vraw = (v <= -800 ? smin : v), sampled at flipped x.
__global__ void __launch_bounds__(256) k_ray(const float* __restrict__ vol,
                                             float* __restrict__ out) {
    int gtid  = blockIdx.x * 256 + threadIdx.x;
    int group = gtid >> 4;                 // ray id
    int lane  = gtid & (KCH - 1);
    int b = (group >= NSUB) ? 1 : 0;
    int n = group - b * NSUB;
    int pix = g_sorted[n];

    float smin = g_scalars[0], dmin = g_scalars[1], inv = g_scalars[2];

    const float* P = g_pose[b];
    float R00 = P[0], R01 = P[1], R02 = P[2];
    float R10 = P[3], R11 = P[4], R12 = P[5];
    float R20 = P[6], R21 = P[7], R22 = P[8];
    float sx_ = P[9], sy_ = P[10], sz_ = P[11];
    float tx  = P[12], ty = P[13], tz = P[14];

    int piy  = pix / 192;
    int pixx = pix - piy * 192;
    float gx = ((float)pixx - 95.5f) * 2.0f;
    float gy = ((float)piy  - 95.5f) * 2.0f;
    const float gz = -300.0f;

    float tgx = fmaf(R02, gz, fmaf(R01, gy, R00 * gx)) + tx;
    float tgy = fmaf(R12, gz, fmaf(R11, gy, R10 * gx)) + ty;
    float tgz = fmaf(R22, gz, fmaf(R21, gy, R20 * gx)) + tz;

    float sdx = tgx - sx_, sdy = tgy - sy_, sdz = tgz - sz_;
    float ssx = (sdx == 0.0f) ? 1e-9f : sdx;
    float ssy = (sdy == 0.0f) ? 1e-9f : sdy;
    float ssz = (sdz == 0.0f) ? 1e-9f : sdz;
    float ivx = 1.0f / ssx, ivy = 1.0f / ssy, ivz = 1.0f / ssz;
    float basex = -sx_ * ivx, basey = -sy_ * ivy, basez = -sz_ * ivz;

    // entry/exit alphas in the SAME fmaf form as the march (bit-identical)
    float ex0 = basex, ex1 = fmaf(192.0f, ivx, basex);
    float ey0 = basey, ey1 = fmaf(192.0f, ivy, basey);
    float ez0 = basez, ez1 = fmaf(192.0f, ivz, basez);

    float amin = fmaxf(fmaxf(fminf(ex0, ex1), fminf(ey0, ey1)), fminf(ez0, ez1));
    amin = fmaxf(amin, 0.0f);
    float amax = fminf(fminf(fmaxf(ex0, ex1), fmaxf(ey0, ey1)), fmaxf(ez0, ez1));
    amax = fminf(amax, 1.0f);
    amax = fmaxf(amax, amin);

    float rl = sqrtf(fmaf(sdx, sdx, fmaf(sdy, sdy, sdz * sdz)));
    float da = (amax - amin) * (1.0f / (float)KCH);
    float as = fmaf((float)lane, da, amin);
    float ae = (lane == KCH - 1) ? amax : fmaf((float)(lane + 1), da, amin);
    ae = fminf(ae, amax);                  // interior lanes: never exceed amax

    float acc = 0.0f;
    if (ae > as) {
        float alx, aly, alz, plx, ply, plz, advx, advy, advz;
        int cxi, cyi, czi, dix, diy, diz;
        ax_init(as, sx_, sdx, ssx, ivx, basex, alx, plx, advx, cxi, dix);
        ax_init(as, sy_, sdy, ssy, ivy, basey, aly, ply, advy, cyi, diy);
        ax_init(as, sz_, sdz, ssz, ivz, basez, alz, plz, advz, czi, diz);

        // linear offset into RAW volume with x flipped: vol[(191-cx)*HW + cy*192 + cz]
        int off  = (191 - cxi) * HW + cyi * 192 + czi;
        int offdx = -dix * HW;       // x cell step moves raw index by -di*HW
        int offdy =  diy * 192;
        int offdz =  diz;

        float cur = fminf(alx, fminf(aly, alz));
        float prev = as;
        while (true) {
            float cseg = fminf(cur, ae);
            float v = __ldg(&vol[off]);
            v = (v <= -800.0f) ? smin : v;
            acc = fmaf(cseg - prev, v, acc);
            if (cur >= ae) break;
            prev = cur;
            // branchless 3-way advance, no validity checks (see ax_init comment)
            bool sxm = (alx <= aly) & (alx <= alz);
            bool sym = (!sxm) & (aly <= alz);
            bool szm = !(sxm | sym);
            float plx2 = plx + 1.0f;
            float ply2 = ply + 1.0f;
            float plz2 = plz + 1.0f;
            off += sxm ? offdx : (sym ? offdy : offdz);
            plx = sxm ? plx2 : plx;   alx = sxm ? fmaf(plx2, advx, basex) : alx;
            ply = sym ? ply2 : ply;   aly = sym ? fmaf(ply2, advy, basey) : aly;
            plz = szm ? plz2 : plz;   alz = szm ? fmaf(plz2, advz, basez) : alz;
            cur = fminf(alx, fminf(aly, alz));
        }
        acc = fmaf(-dmin, ae - as, acc);   // fold (v - dmin)
    }
    acc *= rl * inv;
    #pragma unroll
    for (int o = KCH / 2; o; o >>= 1)
        acc += __shfl_xor_sync(0xffffffffu, acc, o);
    if (lane == 0) out[b * HW + pix] = acc;
}

// ---------------- launch ----------------
extern "C" void kernel_launch(void* const* d_in, const int* in_sizes, int n_in,
                              void* d_out, int out_size) {
    const float* vol = (const float*)d_in[0];
    const float* rot = (const float*)d_in[1];
    const float* tra = (const float*)d_in[2];
    const int*   sub = (const int*)d_in[3];
    float* out = (float*)d_out;

    k_pre<<<RED + 1, 256>>>((const float4*)vol, sub, rot, tra, (float4*)out);
    k_ray<<<(BATCH * NSUB * KCH) / 256, 256>>>(vol, out);
}

// round 17
// speedup vs baseline: 1.1681x; 1.0437x over previous
#include <cuda_runtime.h>

// ---------------- problem constants ----------------
#define HW    36864        // 192*192 detector pixels
#define NSUB  18432        // H*W/2
#define BATCH 2
#define NV4   1769472      // 192^3/4
#define KCH   16           // alpha chunks (lanes) per ray
#define NW    1152         // HW/32 mask words
#define RED   512          // reduction blocks (power of 2 for counter modulo)
#define UNR   4            // marcher unroll (MLP per lane)

#define F_INF __int_as_float(0x7f800000)

// ---------------- device scratch (static, no allocations) ----------------
__device__ float    g_part[RED * 3];
__device__ unsigned g_arrive;        // monotonic; (old & (RED-1)) == RED-1 -> last block
__device__ float    g_scalars[3];    // soft_min, dmin, inv_range
__device__ float    g_pose[BATCH][16];
__device__ int      g_sorted[NSUB];  // subsample pixels in ascending order

// ---------------- launch 1: volume min/max partials + last-block final reduce + pose
//                  (blocks 0..RED-1) | subsample bitmap sort (block RED) | zero output --------
__global__ void __launch_bounds__(256) k_pre(const float4* __restrict__ vol,
                                             const int* __restrict__ sub,
                                             const float* __restrict__ rot,
                                             const float* __restrict__ tra,
                                             float4* __restrict__ out) {
    int gtid = blockIdx.x * 256 + threadIdx.x;
    if (gtid < (BATCH * HW) / 4) out[gtid] = make_float4(0.f, 0.f, 0.f, 0.f);

    if (blockIdx.x == RED) {
        // ---- sort subsample pixels ascending: bitmap + popc compaction ----
        __shared__ unsigned smask[NW];
        __shared__ unsigned spfx[NW];
        int t = threadIdx.x;
        for (int i = t; i < NW; i += 256) smask[i] = 0u;
        __syncthreads();
        for (int i = t; i < NSUB; i += 256) {
            int p = __ldg(&sub[i]);
            atomicOr(&smask[p >> 5], 1u << (p & 31));
        }
        __syncthreads();
        if (t < 32) {
            unsigned run = 0;
            for (int it = 0; it < NW / 32; it++) {
                int w = it * 32 + t;
                unsigned m = smask[w];
                unsigned p = (unsigned)__popc(m);
                unsigned sc = p;
                #pragma unroll
                for (int o = 1; o < 32; o <<= 1) {
                    unsigned v = __shfl_up_sync(0xffffffffu, sc, o);
                    if (t >= o) sc += v;
                }
                spfx[w] = run + sc - p;
                run += __shfl_sync(0xffffffffu, sc, 31);
            }
        }
        __syncthreads();
        for (int i = t; i < HW; i += 256) {
            unsigned m = smask[i >> 5];
            unsigned bit = 1u << (i & 31);
            if (m & bit) {
                int pos = (int)spfx[i >> 5] + __popc(m & (bit - 1u));
                g_sorted[pos] = i;
            }
        }
        return;
    }

    // ---- partial reductions over volume (grid-stride) ----
    float smin = F_INF, omin = F_INF, omax = -F_INF;
    const int stride = RED * 256;
    for (int i = gtid; i < NV4; i += stride) {
        float4 v4 = vol[i];
        float vs[4] = {v4.x, v4.y, v4.z, v4.w};
        #pragma unroll
        for (int c = 0; c < 4; c++) {
            float v = vs[c];
            if (v > -800.0f) {
                omin = fminf(omin, v);
                omax = fmaxf(omax, v);
                if (v <= 350.0f) smin = fminf(smin, v);
            }
        }
    }
    __shared__ float s0[256], s1[256], s2[256];
    __shared__ bool  s_last;
    int t = threadIdx.x;
    s0[t] = smin; s1[t] = omin; s2[t] = omax;
    __syncthreads();
    for (int o = 128; o; o >>= 1) {
        if (t < o) {
            s0[t] = fminf(s0[t], s0[t + o]);
            s1[t] = fminf(s1[t], s1[t + o]);
            s2[t] = fmaxf(s2[t], s2[t + o]);
        }
        __syncthreads();
    }
    if (t == 0) {
        g_part[blockIdx.x * 3 + 0] = s0[0];
        g_part[blockIdx.x * 3 + 1] = s1[0];
        g_part[blockIdx.x * 3 + 2] = s2[0];
    }
    __threadfence();
    if (t == 0) {
        unsigned old = atomicAdd(&g_arrive, 1u);
        s_last = ((old & (RED - 1u)) == (RED - 1u));
    }
    __syncthreads();
    if (!s_last) return;
    __threadfence();

    // ---- last block: final reduce of RED partials + scalars + pose ----
    s0[t] = fminf(g_part[t * 3 + 0], g_part[(t + 256) * 3 + 0]);
    s1[t] = fminf(g_part[t * 3 + 1], g_part[(t + 256) * 3 + 1]);
    s2[t] = fmaxf(g_part[t * 3 + 2], g_part[(t + 256) * 3 + 2]);
    __syncthreads();
    for (int o = 128; o; o >>= 1) {
        if (t < o) {
            s0[t] = fminf(s0[t], s0[t + o]);
            s1[t] = fminf(s1[t], s1[t + o]);
            s2[t] = fmaxf(s2[t], s2[t + o]);
        }
        __syncthreads();
    }
    if (t == 0) {
        float sm = s0[0];
        float dmin = fminf(sm, s1[0]);
        float dmax = fmaxf(sm, s2[0]);
        g_scalars[0] = sm;
        g_scalars[1] = dmin;
        g_scalars[2] = 1.0f / (dmax - dmin);
    }
    if (t < BATCH) {
        int b = t;
        float cz, sz, cy, sy, cx, sx;
        sincosf(rot[b * 3 + 0], &sz, &cz);
        sincosf(rot[b * 3 + 1], &sy, &cy);
        sincosf(rot[b * 3 + 2], &sx, &cx);
        float R00 = cz * cy, R01 = -sz * cx + cz * sy * sx, R02 = sz * sx + cz * sy * cx;
        float R10 = sz * cy, R11 =  cz * cx + sz * sy * sx, R12 = -cz * sx + sz * sy * cx;
        float R20 = -sy,     R21 =  cy * sx,                R22 =  cy * cx;
        float tx = tra[b * 3 + 0] + 96.0f;
        float ty = tra[b * 3 + 1] + 96.0f;
        float tz = tra[b * 3 + 2] + 96.0f;
        float* P = g_pose[b];
        P[0] = R00; P[1] = R01; P[2] = R02;
        P[3] = R10; P[4] = R11; P[5] = R12;
        P[6] = R20; P[7] = R21; P[8] = R22;
        P[9]  = fmaf(R02, 300.0f, tx);   // source = R @ (0,0,300) + t
        P[10] = fmaf(R12, 300.0f, ty);
        P[11] = fmaf(R22, 300.0f, tz);
        P[12] = tx; P[13] = ty; P[14] = tz;
    }
}

// Per-axis merge init at alpha=as. Crossing alpha at absolute plane P is
// ALWAYS fmaf(P, iv, base), base = -src*iv — the same expression used for the
// amin/amax bounds, so the march can never step past a boundary plane while
// cur < ae <= amax.
__device__ __forceinline__ void ax_init(float as, float src, float sd, float ss,
                                        float iv, float base,
                                        float& al, float& pl, float& adv, int& ci, int& di) {
    bool pos = (ss > 0.0f);
    di = pos ? 1 : -1;
    float dfa = (float)di;
    float t = fmaf(as, sd, src);           // position along this axis at alpha=as
    int p;
    if (pos) { p = (int)floorf(t) + 1; if (p < 0)   p = 0;   }
    else     { p = (int)ceilf(t)  - 1; if (p > 192) p = 192; }
    float pf = (float)p;
    al = fmaf(pf, iv, base);
    if (al <= as) { p += di; pf = (float)p; al = fmaf(pf, iv, base); }
    ci = pos ? (p - 1) : p;
    ci = min(191, max(0, ci));
    pl  = pf * dfa;
    adv = dfa * iv;                        // > 0
}

// ---------------- launch 2: raycast on RAW volume (KCH lanes/ray) ----------------
// Software-pipelined UNR segments/iteration: march UNR segments in pure ALU
// (weights + frozen-after-done offsets), then issue UNR independent loads, then
// UNR fmafs. Load latency amortized 1/UNR.
// density fold: out = inv * (sum step*vraw - dmin*(ae-as)) * ray_len,
// vraw = (v <= -800 ? smin : v), sampled at flipped x.
__global__ void __launch_bounds__(256) k_ray(const float* __restrict__ vol,
                                             float* __restrict__ out) {
    int gtid  = blockIdx.x * 256 + threadIdx.x;
    int group = gtid >> 4;                 // ray id
    int lane  = gtid & (KCH - 1);
    int b = (group >= NSUB) ? 1 : 0;
    int n = group - b * NSUB;
    int pix = g_sorted[n];

    float smin = g_scalars[0], dmin = g_scalars[1], inv = g_scalars[2];

    const float* P = g_pose[b];
    float R00 = P[0], R01 = P[1], R02 = P[2];
    float R10 = P[3], R11 = P[4], R12 = P[5];
    float R20 = P[6], R21 = P[7], R22 = P[8];
    float sx_ = P[9], sy_ = P[10], sz_ = P[11];
    float tx  = P[12], ty = P[13], tz = P[14];

    int piy  = pix / 192;
    int pixx = pix - piy * 192;
    float gx = ((float)pixx - 95.5f) * 2.0f;
    float gy = ((float)piy  - 95.5f) * 2.0f;
    const float gz = -300.0f;

    float tgx = fmaf(R02, gz, fmaf(R01, gy, R00 * gx)) + tx;
    float tgy = fmaf(R12, gz, fmaf(R11, gy, R10 * gx)) + ty;
    float tgz = fmaf(R22, gz, fmaf(R21, gy, R20 * gx)) + tz;

    float sdx = tgx - sx_, sdy = tgy - sy_, sdz = tgz - sz_;
    float ssx = (sdx == 0.0f) ? 1e-9f : sdx;
    float ssy = (sdy == 0.0f) ? 1e-9f : sdy;
    float ssz = (sdz == 0.0f) ? 1e-9f : sdz;
    float ivx = 1.0f / ssx, ivy = 1.0f / ssy, ivz = 1.0f / ssz;
    float basex = -sx_ * ivx, basey = -sy_ * ivy, basez = -sz_ * ivz;

    // entry/exit alphas in the SAME fmaf form as the march (bit-identical)
    float ex0 = basex, ex1 = fmaf(192.0f, ivx, basex);
    float ey0 = basey, ey1 = fmaf(192.0f, ivy, basey);
    float ez0 = basez, ez1 = fmaf(192.0f, ivz, basez);

    float amin = fmaxf(fmaxf(fminf(ex0, ex1), fminf(ey0, ey1)), fminf(ez0, ez1));
    amin = fmaxf(amin, 0.0f);
    float amax = fminf(fminf(fmaxf(ex0, ex1), fmaxf(ey0, ey1)), fmaxf(ez0, ez1));
    amax = fminf(amax, 1.0f);
    amax = fmaxf(amax, amin);

    float rl = sqrtf(fmaf(sdx, sdx, fmaf(sdy, sdy, sdz * sdz)));
    float da = (amax - amin) * (1.0f / (float)KCH);
    float as = fmaf((float)lane, da, amin);
    float ae = (lane == KCH - 1) ? amax : fmaf((float)(lane + 1), da, amin);
    ae = fminf(ae, amax);                  // interior lanes: never exceed amax

    float acc = 0.0f;
    if (ae > as) {
        float alx, aly, alz, plx, ply, plz, advx, advy, advz;
        int cxi, cyi, czi, dix, diy, diz;
        ax_init(as, sx_, sdx, ssx, ivx, basex, alx, plx, advx, cxi, dix);
        ax_init(as, sy_, sdy, ssy, ivy, basey, aly, ply, advy, cyi, diy);
        ax_init(as, sz_, sdz, ssz, ivz, basez, alz, plz, advz, czi, diz);

        // linear offset into RAW volume with x flipped: vol[(191-cx)*HW + cy*192 + cz]
        int off  = (191 - cxi) * HW + cyi * 192 + czi;
        int offdx = -dix * HW;       // x cell step moves raw index by -di*HW
        int offdy =  diy * 192;
        int offdz =  diz;

        float cur = fminf(alx, fminf(aly, alz));
        float prev = as;
        while (prev < ae) {
            int   offs[UNR];
            float wts[UNR];
            #pragma unroll
            for (int u = 0; u < UNR; u++) {
                float cseg = fminf(cur, ae);
                wts[u]  = cseg - prev;       // 0 for finished lanes
                prev    = cseg;              // == ae once finished (exact)
                offs[u] = off;
                bool fin = (cur >= ae);
                bool sxm = (alx <= aly) & (alx <= alz);
                bool sym = (!sxm) & (aly <= alz);
                bool szm = !(sxm | sym);
                int step = fin ? 0 : (sxm ? offdx : (sym ? offdy : offdz));
                off += step;                 // frozen after finish -> stays in-bounds
                float plx2 = plx + 1.0f;
                float ply2 = ply + 1.0f;
                float plz2 = plz + 1.0f;
                plx = sxm ? plx2 : plx;   alx = sxm ? fmaf(plx2, advx, basex) : alx;
                ply = sym ? ply2 : ply;   aly = sym ? fmaf(ply2, advy, basey) : aly;
                plz = szm ? plz2 : plz;   alz = szm ? fmaf(plz2, advz, basez) : alz;
                cur = fminf(alx, fminf(aly, alz));
            }
            float vs[UNR];
            #pragma unroll
            for (int u = 0; u < UNR; u++)
                vs[u] = __ldg(&vol[offs[u]]);    // UNR independent loads in flight
            #pragma unroll
            for (int u = 0; u < UNR; u++) {
                float v = (vs[u] <= -800.0f) ? smin : vs[u];
                acc = fmaf(wts[u], v, acc);
            }
        }
        acc = fmaf(-dmin, ae - as, acc);   // fold (v - dmin)
    }
    acc *= rl * inv;
    #pragma unroll
    for (int o = KCH / 2; o; o >>= 1)
        acc += __shfl_xor_sync(0xffffffffu, acc, o);
    if (lane == 0) out[b * HW + pix] = acc;
}

// ---------------- launch ----------------
extern "C" void kernel_launch(void* const* d_in, const int* in_sizes, int n_in,
                              void* d_out, int out_size) {
    const float* vol = (const float*)d_in[0];
    const float* rot = (const float*)d_in[1];
    const float* tra = (const float*)d_in[2];
    const int*   sub = (const int*)d_in[3];
    float* out = (float*)d_out;

    k_pre<<<RED + 1, 256>>>((const float4*)vol, sub, rot, tra, (float4*)out);
    k_ray<<<(BATCH * NSUB * KCH) / 256, 256>>>(vol, out);
}